// round 15
// baseline (speedup 1.0000x reference)
#include <cuda_runtime.h>
#include <cuda_fp16.h>
#include <math.h>
#include <stdint.h>

#define DIMV    2048
#define NHEADS  16
#define HD      128
#define HIDDEN  8192
#define BATCH   2
#define SEQ     2048
#define MTOT    (BATCH*SEQ)
#define QKVS    (3*DIMV)
#define EPSV    1e-6f

// ---------------- scratch ----------------
__device__ __half g_xnh [MTOT*DIMV];
__device__ __half g_qkv [MTOT*QKVS];
__device__ __half g_ath [MTOT*DIMV];
__device__ float  g_h   [MTOT*DIMV];
__device__ __half g_g1h [MTOT*HIDDEN];
__device__ __half g_wqkvT[3*DIMV*DIMV];
__device__ __half g_woT [DIMV*DIMV];
__device__ __half g_w13i[2*HIDDEN*DIMV];
__device__ __half g_w2T [DIMV*HIDDEN];

__device__ __forceinline__ uint32_t smem_u32(const void* p) {
    uint32_t a;
    asm("{ .reg .u64 t; cvta.to.shared.u64 t, %1; cvt.u32.u64 %0, t; }" : "=r"(a) : "l"(p));
    return a;
}
__device__ __forceinline__ uint32_t h2_to_u32(__half2 h) {
    union { __half2 h2; uint32_t u; } cvt;
    cvt.h2 = h;
    return cvt.u;
}
__device__ __forceinline__ void mma16816(float* c, const uint32_t* a, const uint32_t* b) {
    asm volatile("mma.sync.aligned.m16n8k16.row.col.f32.f16.f16.f32 "
        "{%0,%1,%2,%3}, {%4,%5,%6,%7}, {%8,%9}, {%0,%1,%2,%3};"
        : "+f"(c[0]), "+f"(c[1]), "+f"(c[2]), "+f"(c[3])
        : "r"(a[0]), "r"(a[1]), "r"(a[2]), "r"(a[3]), "r"(b[0]), "r"(b[1]));
}
__device__ __forceinline__ void ldsm_x4(uint32_t* r, uint32_t addr) {
    asm volatile("ldmatrix.sync.aligned.m8n8.x4.shared.b16 {%0,%1,%2,%3}, [%4];"
        : "=r"(r[0]), "=r"(r[1]), "=r"(r[2]), "=r"(r[3]) : "r"(addr));
}
__device__ __forceinline__ void ldsm_x4_t(uint32_t* r, uint32_t addr) {
    asm volatile("ldmatrix.sync.aligned.m8n8.x4.trans.shared.b16 {%0,%1,%2,%3}, [%4];"
        : "=r"(r[0]), "=r"(r[1]), "=r"(r[2]), "=r"(r[3]) : "r"(addr));
}

// ---------------- RMSNorm (fp32 in, half out) ----------------
__global__ __launch_bounds__(256) void rmsnorm_kernel(
    const float* __restrict__ x, const float* __restrict__ w, __half* __restrict__ y)
{
    int row = blockIdx.x;
    const float* xr = x + (size_t)row * DIMV;
    float ss = 0.f;
    for (int i = threadIdx.x * 4; i < DIMV; i += blockDim.x * 4) {
        float4 v = *(const float4*)(xr + i);
        ss += v.x*v.x + v.y*v.y + v.z*v.z + v.w*v.w;
    }
    __shared__ float red[8];
    for (int o = 16; o > 0; o >>= 1) ss += __shfl_down_sync(0xffffffffu, ss, o);
    int warp = threadIdx.x >> 5, lane = threadIdx.x & 31;
    if (lane == 0) red[warp] = ss;
    __syncthreads();
    if (warp == 0) {
        float t = (lane < 8) ? red[lane] : 0.f;
        for (int o = 4; o > 0; o >>= 1) t += __shfl_down_sync(0xffffffffu, t, o);
        if (lane == 0) red[0] = t;
    }
    __syncthreads();
    float r = rsqrtf(red[0] / (float)DIMV + EPSV);
    __half* yr = y + (size_t)row * DIMV;
    for (int i = threadIdx.x * 4; i < DIMV; i += blockDim.x * 4) {
        float4 v = *(const float4*)(xr + i);
        float4 ww = *(const float4*)(w + i);
        *(__half2*)(yr + i)     = __floats2half2_rn(v.x * r * ww.x, v.y * r * ww.y);
        *(__half2*)(yr + i + 2) = __floats2half2_rn(v.z * r * ww.z, v.w * r * ww.w);
    }
}

// ---------------- transpose + fp32->half, 64x128 tiles, float4 loads ----------------
// src: rows indexed by blockIdx.y*64 (row length C); dst row (istride*(bx+col)+ioff), length R.
__global__ __launch_bounds__(256) void transpose_h_kernel(
    const float* __restrict__ src, __half* __restrict__ dst, int R, int C,
    int istride, int ioff)
{
    __shared__ float t[64][129];
    int bx = blockIdx.x * 128, by = blockIdx.y * 64;
    int tx = threadIdx.x & 31, ty = threadIdx.x >> 5;   // 32 x 8
    #pragma unroll
    for (int i = 0; i < 8; i++) {
        int row = i * 8 + ty;
        float4 v = *(const float4*)(src + (size_t)(by + row) * C + bx + 4 * tx);
        t[row][4 * tx + 0] = v.x;
        t[row][4 * tx + 1] = v.y;
        t[row][4 * tx + 2] = v.z;
        t[row][4 * tx + 3] = v.w;
    }
    __syncthreads();
    #pragma unroll
    for (int j = 0; j < 16; j++) {
        int col = j * 8 + ty;
        __half2 v = __floats2half2_rn(t[2 * tx][col], t[2 * tx + 1][col]);
        *(__half2*)(dst + (size_t)(istride * (bx + col) + ioff) * R + by + 2 * tx) = v;
    }
}

// ---------------- HMMA fp16 GEMM, 128x128 tile, GBK=64, ring-3, 2 CTAs/SM ----------------
// MODE 0: fp32 out (+R residual);  MODE 2: half out + RoPE for n<2*DIMV;
// MODE 3: swiglu (B col-interleaved w1/w3), half out at col n/2
#define GBM 128
#define GBN 128
#define GBK 64
#define APAD 72                 // halves per row (144B stride -> conflict-free ldmatrix)
#define TILE_H (128*APAD)       // halves per (A or B) tile
#define STAGE_H (2*TILE_H)      // halves per stage (A then B)

template <int MODE>
__global__ __launch_bounds__(256, 2) void gemm_hmma(
    const __half* __restrict__ A, const __half* __restrict__ Bt,
    const float* __restrict__ R, float* __restrict__ Cf, __half* __restrict__ Ch,
    const float* __restrict__ cs, const float* __restrict__ sn,
    int Mn, int Nn, int Kn)
{
    extern __shared__ __half hs[];
    const int tid = threadIdx.x;
    const int lane = tid & 31, wid = tid >> 5;
    const int wm = wid >> 2, wn = wid & 3;
    const int bm = blockIdx.y * GBM, bn = blockIdx.x * GBN;

    float acc[4][4][4];
    #pragma unroll
    for (int i = 0; i < 4; i++)
        #pragma unroll
        for (int j = 0; j < 4; j++)
            #pragma unroll
            for (int q = 0; q < 4; q++) acc[i][j][q] = 0.f;

    const __half* Ag = A + (size_t)bm * Kn;
    const __half* Bg = Bt + (size_t)bn * Kn;
    const int r0 = tid >> 3, c0 = (tid & 7) * 8;   // 32 rows per pass, 64 halves/row
    const uint32_t s0a = smem_u32(hs);
    const int NC = Kn / GBK;

#define ISSUE(stage, c)                                                              \
    {                                                                                \
        int kb = (c) * GBK;                                                          \
        uint32_t sA = s0a + (stage) * STAGE_H * 2;                                   \
        uint32_t sB = sA + TILE_H * 2;                                               \
        _Pragma("unroll")                                                            \
        for (int ii = 0; ii < 4; ii++) {                                             \
            int row = r0 + ii * 32;                                                  \
            asm volatile("cp.async.cg.shared.global [%0], [%1], 16;"                 \
                :: "r"(sA + (row * APAD + c0) * 2), "l"(Ag + (size_t)row * Kn + kb + c0)); \
            asm volatile("cp.async.cg.shared.global [%0], [%1], 16;"                 \
                :: "r"(sB + (row * APAD + c0) * 2), "l"(Bg + (size_t)row * Kn + kb + c0)); \
        }                                                                            \
        asm volatile("cp.async.commit_group;" ::: "memory");                         \
    }

    ISSUE(0, 0);
    ISSUE(1, 1);

    for (int c = 0; c < NC; c++) {
        const int s = c - (c / 3) * 3;   // c % 3
        if (c + 1 < NC) asm volatile("cp.async.wait_group 1;" ::: "memory");
        else            asm volatile("cp.async.wait_group 0;" ::: "memory");
        __syncthreads();
        if (c + 2 < NC) {
            int s2 = (c + 2) - ((c + 2) / 3) * 3;
            ISSUE(s2, c + 2);
        }
        const uint32_t aBase = s0a + s * STAGE_H * 2;
        const uint32_t bBase = aBase + TILE_H * 2;
        #pragma unroll
        for (int kk = 0; kk < 4; kk++) {
            uint32_t afr[4][4], bfr[4][2];
            #pragma unroll
            for (int mi = 0; mi < 4; mi++) {
                int row = wm * 64 + mi * 16 + (lane & 15);
                int col = kk * 16 + (lane >> 4) * 8;
                ldsm_x4(afr[mi], aBase + (row * APAD + col) * 2);
            }
            #pragma unroll
            for (int jp = 0; jp < 2; jp++) {
                uint32_t t4[4];
                int row = wn * 32 + (jp * 2 + (lane >> 4)) * 8 + (lane & 7);
                int col = kk * 16 + ((lane >> 3) & 1) * 8;
                ldsm_x4(t4, bBase + (row * APAD + col) * 2);
                bfr[jp*2][0] = t4[0]; bfr[jp*2][1] = t4[1];
                bfr[jp*2+1][0] = t4[2]; bfr[jp*2+1][1] = t4[3];
            }
            #pragma unroll
            for (int mi = 0; mi < 4; mi++)
                #pragma unroll
                for (int ni = 0; ni < 4; ni++)
                    mma16816(acc[mi][ni], afr[mi], bfr[ni]);
        }
    }
#undef ISSUE

    #pragma unroll
    for (int mi = 0; mi < 4; mi++) {
        int mrow0 = bm + wm * 64 + mi * 16 + (lane >> 2);
        #pragma unroll
        for (int hh = 0; hh < 2; hh++) {
            int m = mrow0 + hh * 8;
            int nb = bn + wn * 32 + 2 * (lane & 3);
            #pragma unroll
            for (int ni = 0; ni < 4; ni++) {
                int n = nb + ni * 8;
                float va = acc[mi][ni][hh * 2 + 0], vb = acc[mi][ni][hh * 2 + 1];
                if (MODE == 0) {
                    size_t off = (size_t)m * Nn + n;
                    if (R) {
                        float2 rv = *(const float2*)(R + off);
                        va += rv.x; vb += rv.y;
                    }
                    *(float2*)(Cf + off) = make_float2(va, vb);
                } else if (MODE == 2) {
                    size_t off = (size_t)m * Nn + n;
                    if (n < 2 * DIMV) {
                        int i2 = (n & (HD - 1)) >> 1;
                        int sidx = m & (SEQ - 1);
                        float cc = cs[sidx * (HD / 2) + i2];
                        float si = sn[sidx * (HD / 2) + i2];
                        float ra = va * cc - vb * si;
                        float rb = va * si + vb * cc;
                        *(__half2*)(Ch + off) = __floats2half2_rn(ra, rb);
                    } else {
                        *(__half2*)(Ch + off) = __floats2half2_rn(va, vb);
                    }
                } else {  // swiglu
                    float g = va / (1.f + __expf(-va)) * vb;
                    Ch[(size_t)m * (Nn >> 1) + (n >> 1)] = __float2half(g);
                }
            }
        }
    }
}

// ---------------- Flash attention, fp16 mma, causal, ring-3, exp2 softmax ----------------
#define BQ  128
#define BKV 64
#define KVS 136

__global__ __launch_bounds__(256) void attn_mma(
    const __half* __restrict__ QKV, __half* __restrict__ O)
{
    extern __shared__ __half kvsm[];
    __half* Ks = kvsm;                     // ring of 3
    __half* Vs = kvsm + 3 * BKV * KVS;     // ring of 3
    const int tid = threadIdx.x, lane = tid & 31, w = tid >> 5;
    const int qt = gridDim.x - 1 - blockIdx.x;   // heavy blocks first
    const int bh = blockIdx.y;
    const int b = bh >> 4, h = bh & 15;
    const int q0 = qt * BQ;
    const int r = lane >> 2, cq = (lane & 3) * 2;
    const float scale2 = 0.08838834764831845f * 1.4426950408889634f;  // /sqrt(128) * log2(e)

    uint32_t qf[8][4];
    {
        const __half* Qg  = QKV + (size_t)(b * SEQ + q0 + w * 16 + r) * QKVS + h * HD;
        const __half* Qg8 = Qg + 8 * (size_t)QKVS;
        #pragma unroll
        for (int kk = 0; kk < 8; kk++) {
            qf[kk][0] = *(const uint32_t*)(Qg  + kk * 16 + cq);
            qf[kk][1] = *(const uint32_t*)(Qg8 + kk * 16 + cq);
            qf[kk][2] = *(const uint32_t*)(Qg  + kk * 16 + 8 + cq);
            qf[kk][3] = *(const uint32_t*)(Qg8 + kk * 16 + 8 + cq);
        }
    }

    float oacc[16][4];
    #pragma unroll
    for (int j = 0; j < 16; j++)
        #pragma unroll
        for (int q = 0; q < 4; q++) oacc[j][q] = 0.f;
    float m0 = -1e30f, m1 = -1e30f, l0 = 0.f, l1 = 0.f;

    const uint32_t sKs = smem_u32(Ks), sVs = smem_u32(Vs);
    const __half* Kg = QKV + (size_t)(b * SEQ) * QKVS + DIMV + h * HD;
    const __half* Vg = QKV + (size_t)(b * SEQ) * QKVS + 2 * DIMV + h * HD;
    const int nkt = qt * 2 + 2;

#define KV_ISSUE(stage, kt)                                                        \
    {                                                                              \
        _Pragma("unroll")                                                          \
        for (int ii = 0; ii < 4; ii++) {                                           \
            int idx = tid + ii * 256;                                              \
            int rr = idx >> 4, cc = (idx & 15) * 8;                                \
            uint32_t doff = (uint32_t)(((stage) * BKV + rr) * KVS + cc) * 2;       \
            asm volatile("cp.async.cg.shared.global [%0], [%1], 16;"               \
                :: "r"(sKs + doff), "l"(Kg + (size_t)((kt) * BKV + rr) * QKVS + cc)); \
            asm volatile("cp.async.cg.shared.global [%0], [%1], 16;"               \
                :: "r"(sVs + doff), "l"(Vg + (size_t)((kt) * BKV + rr) * QKVS + cc)); \
        }                                                                          \
        asm volatile("cp.async.commit_group;" ::: "memory");                       \
    }

    KV_ISSUE(0, 0);
    if (nkt > 1) KV_ISSUE(1, 1);

    for (int kt = 0; kt < nkt; kt++) {
        const int s = kt - (kt / 3) * 3;
        if (kt + 1 < nkt) asm volatile("cp.async.wait_group 1;" ::: "memory");
        else              asm volatile("cp.async.wait_group 0;" ::: "memory");
        __syncthreads();
        if (kt + 2 < nkt) {
            int s2 = (kt + 2) - ((kt + 2) / 3) * 3;
            KV_ISSUE(s2, kt + 2);
        }
        const uint32_t kb = sKs + (uint32_t)(s * BKV * KVS) * 2;
        const uint32_t vb = sVs + (uint32_t)(s * BKV * KVS) * 2;

        float sa[8][4];
        #pragma unroll
        for (int j = 0; j < 8; j++)
            #pragma unroll
            for (int q = 0; q < 4; q++) sa[j][q] = 0.f;
        #pragma unroll
        for (int kk = 0; kk < 8; kk++) {
            uint32_t kf[8][2];
            #pragma unroll
            for (int jp = 0; jp < 4; jp++) {
                uint32_t t4[4];
                int nt = jp * 2 + (lane >> 4);
                uint32_t addr = kb + (uint32_t)((nt * 8 + (lane & 7)) * KVS
                                + kk * 16 + ((lane >> 3) & 1) * 8) * 2;
                ldsm_x4(t4, addr);
                kf[jp*2][0] = t4[0]; kf[jp*2][1] = t4[1];
                kf[jp*2+1][0] = t4[2]; kf[jp*2+1][1] = t4[3];
            }
            #pragma unroll
            for (int j = 0; j < 8; j++)
                mma16816(sa[j], qf[kk], kf[j]);
        }

        // log2-domain online softmax
        const int row0 = q0 + w * 16 + r, row1 = row0 + 8;
        const bool need_mask = (kt * BKV + BKV - 1) > row0 || (kt * BKV + BKV - 1) > row1;
        float mx0 = -1e30f, mx1 = -1e30f;
        #pragma unroll
        for (int j = 0; j < 8; j++) {
            int col = kt * BKV + j * 8 + cq;
            sa[j][0] *= scale2; sa[j][1] *= scale2;
            sa[j][2] *= scale2; sa[j][3] *= scale2;
            if (need_mask) {
                if (col     > row0) sa[j][0] = -1e30f;
                if (col + 1 > row0) sa[j][1] = -1e30f;
                if (col     > row1) sa[j][2] = -1e30f;
                if (col + 1 > row1) sa[j][3] = -1e30f;
            }
            mx0 = fmaxf(mx0, fmaxf(sa[j][0], sa[j][1]));
            mx1 = fmaxf(mx1, fmaxf(sa[j][2], sa[j][3]));
        }
        mx0 = fmaxf(mx0, __shfl_xor_sync(0xffffffffu, mx0, 1));
        mx0 = fmaxf(mx0, __shfl_xor_sync(0xffffffffu, mx0, 2));
        mx1 = fmaxf(mx1, __shfl_xor_sync(0xffffffffu, mx1, 1));
        mx1 = fmaxf(mx1, __shfl_xor_sync(0xffffffffu, mx1, 2));
        float mn0 = fmaxf(m0, mx0), mn1 = fmaxf(m1, mx1);
        float a0 = exp2f(m0 - mn0), a1 = exp2f(m1 - mn1);
        float s0 = 0.f, s1 = 0.f;
        uint32_t ph[8][2];
        #pragma unroll
        for (int j = 0; j < 8; j++) {
            float p00 = exp2f(sa[j][0] - mn0);
            float p01 = exp2f(sa[j][1] - mn0);
            float p10 = exp2f(sa[j][2] - mn1);
            float p11 = exp2f(sa[j][3] - mn1);
            s0 += p00 + p01; s1 += p10 + p11;
            ph[j][0] = h2_to_u32(__floats2half2_rn(p00, p01));
            ph[j][1] = h2_to_u32(__floats2half2_rn(p10, p11));
        }
        s0 += __shfl_xor_sync(0xffffffffu, s0, 1);
        s0 += __shfl_xor_sync(0xffffffffu, s0, 2);
        s1 += __shfl_xor_sync(0xffffffffu, s1, 1);
        s1 += __shfl_xor_sync(0xffffffffu, s1, 2);
        l0 = l0 * a0 + s0; l1 = l1 * a1 + s1;
        m0 = mn0; m1 = mn1;
        #pragma unroll
        for (int j = 0; j < 16; j++) {
            oacc[j][0] *= a0; oacc[j][1] *= a0;
            oacc[j][2] *= a1; oacc[j][3] *= a1;
        }

        #pragma unroll
        for (int kk2 = 0; kk2 < 4; kk2++) {
            uint32_t pa[4] = { ph[kk2*2][0], ph[kk2*2][1], ph[kk2*2+1][0], ph[kk2*2+1][1] };
            #pragma unroll
            for (int jp = 0; jp < 8; jp++) {
                uint32_t vt[4];
                uint32_t addr = vb + (uint32_t)((kk2 * 16 + (lane & 15)) * KVS
                                + (jp * 2 + (lane >> 4)) * 8) * 2;
                ldsm_x4_t(vt, addr);
                mma16816(oacc[jp*2],     pa, &vt[0]);
                mma16816(oacc[jp*2 + 1], pa, &vt[2]);
            }
        }
    }
#undef KV_ISSUE

    float i0 = 1.f / l0, i1 = 1.f / l1;
    __half* Og  = O + (size_t)(b * SEQ + q0 + w * 16 + r) * DIMV + h * HD + cq;
    __half* Og8 = Og + 8 * (size_t)DIMV;
    #pragma unroll
    for (int j = 0; j < 16; j++) {
        *(__half2*)(Og  + j * 8) = __floats2half2_rn(oacc[j][0] * i0, oacc[j][1] * i0);
        *(__half2*)(Og8 + j * 8) = __floats2half2_rn(oacc[j][2] * i1, oacc[j][3] * i1);
    }
}

// ---------------- launch ----------------
extern "C" void kernel_launch(void* const* d_in, const int* in_sizes, int n_in,
                              void* d_out, int out_size)
{
    const float* x    = (const float*)d_in[0];
    const float* fcos = (const float*)d_in[1];
    const float* fsin = (const float*)d_in[2];
    const float* wq   = (const float*)d_in[4];
    const float* wk   = (const float*)d_in[5];
    const float* wv   = (const float*)d_in[6];
    const float* wo   = (const float*)d_in[7];
    const float* w1   = (const float*)d_in[8];
    const float* w2   = (const float*)d_in[9];
    const float* w3   = (const float*)d_in[10];
    const float* anw  = (const float*)d_in[11];
    const float* fnw  = (const float*)d_in[12];
    float* out = (float*)d_out;

    __half *xnh, *qkv, *ath, *g1h;
    float *h;
    __half *wqkvT, *woT, *w13i, *w2T;
    cudaGetSymbolAddress((void**)&xnh,   g_xnh);
    cudaGetSymbolAddress((void**)&qkv,   g_qkv);
    cudaGetSymbolAddress((void**)&ath,   g_ath);
    cudaGetSymbolAddress((void**)&h,     g_h);
    cudaGetSymbolAddress((void**)&g1h,   g_g1h);
    cudaGetSymbolAddress((void**)&wqkvT, g_wqkvT);
    cudaGetSymbolAddress((void**)&woT,   g_woT);
    cudaGetSymbolAddress((void**)&w13i,  g_w13i);
    cudaGetSymbolAddress((void**)&w2T,   g_w2T);

    const int gemm_smem = 3 * STAGE_H * (int)sizeof(__half);   // 110592
    cudaFuncSetAttribute(gemm_hmma<0>, cudaFuncAttributeMaxDynamicSharedMemorySize, gemm_smem);
    cudaFuncSetAttribute(gemm_hmma<2>, cudaFuncAttributeMaxDynamicSharedMemorySize, gemm_smem);
    cudaFuncSetAttribute(gemm_hmma<3>, cudaFuncAttributeMaxDynamicSharedMemorySize, gemm_smem);
    const int attn_smem = 6 * BKV * KVS * (int)sizeof(__half);  // 104448
    cudaFuncSetAttribute(attn_mma, cudaFuncAttributeMaxDynamicSharedMemorySize, attn_smem);

    dim3 blk(256);
    // launches 0-3: transposes needed before qkv / wo GEMMs (64-row x 128-col tiles)
    transpose_h_kernel<<<dim3(DIMV/128, DIMV/64), blk>>>(wq, wqkvT,               DIMV, DIMV, 1, 0);
    transpose_h_kernel<<<dim3(DIMV/128, DIMV/64), blk>>>(wk, wqkvT + DIMV*DIMV,   DIMV, DIMV, 1, 0);
    transpose_h_kernel<<<dim3(DIMV/128, DIMV/64), blk>>>(wv, wqkvT + 2*DIMV*DIMV, DIMV, DIMV, 1, 0);
    transpose_h_kernel<<<dim3(DIMV/128, DIMV/64), blk>>>(wo, woT, DIMV, DIMV, 1, 0);

    // launch 4: rmsnorm
    rmsnorm_kernel<<<MTOT, 256>>>(x, anw, xnh);

    // launch 5: qkv GEMM (profiled by ncu -s 5 -c 1)
    gemm_hmma<2><<<dim3(QKVS / GBN, MTOT / GBM), 256, gemm_smem>>>(
        xnh, wqkvT, nullptr, nullptr, qkv, fcos, fsin, MTOT, QKVS, DIMV);

    // launch 6: attention
    attn_mma<<<dim3(SEQ / BQ, BATCH * NHEADS), 256, attn_smem>>>(qkv, ath);

    // launches 7-9: remaining weight preps (before their consumers)
    transpose_h_kernel<<<dim3(HIDDEN/128, DIMV/64), blk>>>(w1, w13i, DIMV, HIDDEN, 2, 0);
    transpose_h_kernel<<<dim3(HIDDEN/128, DIMV/64), blk>>>(w3, w13i, DIMV, HIDDEN, 2, 1);
    transpose_h_kernel<<<dim3(DIMV/128, HIDDEN/64), blk>>>(w2, w2T, HIDDEN, DIMV, 1, 0);

    // h = x + at @ wo
    gemm_hmma<0><<<dim3(DIMV / GBN, MTOT / GBM), 256, gemm_smem>>>(
        ath, woT, x, h, nullptr, nullptr, nullptr, MTOT, DIMV, DIMV);

    // hn = rmsnorm(h)
    rmsnorm_kernel<<<MTOT, 256>>>(h, fnw, xnh);

    // g1 = silu(hn@w1) * (hn@w3)
    gemm_hmma<3><<<dim3(2 * HIDDEN / GBN, MTOT / GBM), 256, gemm_smem>>>(
        xnh, w13i, nullptr, nullptr, g1h, nullptr, nullptr, MTOT, 2 * HIDDEN, DIMV);

    // out = h + g1 @ w2
    gemm_hmma<0><<<dim3(DIMV / GBN, MTOT / GBM), 256, gemm_smem>>>(
        g1h, w2T, h, out, nullptr, nullptr, nullptr, MTOT, DIMV, HIDDEN);
}

// round 16
// speedup vs baseline: 1.0150x; 1.0150x over previous
#include <cuda_runtime.h>
#include <cuda_fp16.h>
#include <math.h>
#include <stdint.h>

#define DIMV    2048
#define NHEADS  16
#define HD      128
#define HIDDEN  8192
#define BATCH   2
#define SEQ     2048
#define MTOT    (BATCH*SEQ)
#define QKVS    (3*DIMV)
#define EPSV    1e-6f

// ---------------- scratch ----------------
__device__ __half g_xnh  [MTOT*DIMV];
__device__ __half g_qkv  [MTOT*QKVS];
__device__ __half g_ath  [MTOT*DIMV];
__device__ float  g_h    [MTOT*DIMV];
__device__ __half g_g1h  [MTOT*HIDDEN];
__device__ __half g_wqkvKN[DIMV*QKVS];      // [K=2048][N=6144] concat q|k|v
__device__ __half g_woKN [DIMV*DIMV];       // [K][N]
__device__ __half g_w13i [DIMV*2*HIDDEN];   // [K][16384] interleaved w1/w3 cols
__device__ __half g_w2KN [HIDDEN*DIMV];     // [K=8192][N=2048]

__device__ __forceinline__ uint32_t smem_u32(const void* p) {
    uint32_t a;
    asm("{ .reg .u64 t; cvta.to.shared.u64 t, %1; cvt.u32.u64 %0, t; }" : "=r"(a) : "l"(p));
    return a;
}
__device__ __forceinline__ uint32_t h2_to_u32(__half2 h) {
    union { __half2 h2; uint32_t u; } cvt;
    cvt.h2 = h;
    return cvt.u;
}
__device__ __forceinline__ void mma16816(float* c, const uint32_t* a, const uint32_t* b) {
    asm volatile("mma.sync.aligned.m16n8k16.row.col.f32.f16.f16.f32 "
        "{%0,%1,%2,%3}, {%4,%5,%6,%7}, {%8,%9}, {%0,%1,%2,%3};"
        : "+f"(c[0]), "+f"(c[1]), "+f"(c[2]), "+f"(c[3])
        : "r"(a[0]), "r"(a[1]), "r"(a[2]), "r"(a[3]), "r"(b[0]), "r"(b[1]));
}
__device__ __forceinline__ void ldsm_x4(uint32_t* r, uint32_t addr) {
    asm volatile("ldmatrix.sync.aligned.m8n8.x4.shared.b16 {%0,%1,%2,%3}, [%4];"
        : "=r"(r[0]), "=r"(r[1]), "=r"(r[2]), "=r"(r[3]) : "r"(addr));
}
__device__ __forceinline__ void ldsm_x4_t(uint32_t* r, uint32_t addr) {
    asm volatile("ldmatrix.sync.aligned.m8n8.x4.trans.shared.b16 {%0,%1,%2,%3}, [%4];"
        : "=r"(r[0]), "=r"(r[1]), "=r"(r[2]), "=r"(r[3]) : "r"(addr));
}

// ---------------- RMSNorm (fp32 in, half out) ----------------
__global__ __launch_bounds__(256) void rmsnorm_kernel(
    const float* __restrict__ x, const float* __restrict__ w, __half* __restrict__ y)
{
    int row = blockIdx.x;
    const float* xr = x + (size_t)row * DIMV;
    float ss = 0.f;
    for (int i = threadIdx.x * 4; i < DIMV; i += blockDim.x * 4) {
        float4 v = *(const float4*)(xr + i);
        ss += v.x*v.x + v.y*v.y + v.z*v.z + v.w*v.w;
    }
    __shared__ float red[8];
    for (int o = 16; o > 0; o >>= 1) ss += __shfl_down_sync(0xffffffffu, ss, o);
    int warp = threadIdx.x >> 5, lane = threadIdx.x & 31;
    if (lane == 0) red[warp] = ss;
    __syncthreads();
    if (warp == 0) {
        float t = (lane < 8) ? red[lane] : 0.f;
        for (int o = 4; o > 0; o >>= 1) t += __shfl_down_sync(0xffffffffu, t, o);
        if (lane == 0) red[0] = t;
    }
    __syncthreads();
    float r = rsqrtf(red[0] / (float)DIMV + EPSV);
    __half* yr = y + (size_t)row * DIMV;
    for (int i = threadIdx.x * 4; i < DIMV; i += blockDim.x * 4) {
        float4 v = *(const float4*)(xr + i);
        float4 ww = *(const float4*)(w + i);
        *(__half2*)(yr + i)     = __floats2half2_rn(v.x * r * ww.x, v.y * r * ww.y);
        *(__half2*)(yr + i + 2) = __floats2half2_rn(v.z * r * ww.z, v.w * r * ww.w);
    }
}

// ---------------- fp32 -> half streaming convert (keeps [K][N] layout; row restride) ----------------
// src [K][N]; dst row k at dst + k*dstStride + dstOff, contiguous N elems.
__global__ __launch_bounds__(256) void convf2h_kernel(
    const float* __restrict__ src, __half* __restrict__ dst,
    int N, int dstStride, int dstOff)
{
    size_t i = ((size_t)blockIdx.x * 256 + threadIdx.x) * 8;
    int k = (int)(i / N);
    int n = (int)(i - (size_t)k * N);
    float4 a = *(const float4*)(src + i);
    float4 b = *(const float4*)(src + i + 4);
    __half* d = dst + (size_t)k * dstStride + dstOff + n;
    *(__half2*)(d)     = __floats2half2_rn(a.x, a.y);
    *(__half2*)(d + 2) = __floats2half2_rn(a.z, a.w);
    *(__half2*)(d + 4) = __floats2half2_rn(b.x, b.y);
    *(__half2*)(d + 6) = __floats2half2_rn(b.z, b.w);
}

// interleave w1/w3 columns: dst[k][2j]=w1[k][j], dst[k][2j+1]=w3[k][j]  (contiguous 16B writes)
__global__ __launch_bounds__(256) void conv_interleave_kernel(
    const float* __restrict__ w1, const float* __restrict__ w3,
    __half* __restrict__ dst, int N)
{
    size_t i = ((size_t)blockIdx.x * 256 + threadIdx.x) * 4;
    float4 a = *(const float4*)(w1 + i);
    float4 b = *(const float4*)(w3 + i);
    __half* d = dst + i * 2;
    *(__half2*)(d)     = __floats2half2_rn(a.x, b.x);
    *(__half2*)(d + 2) = __floats2half2_rn(a.y, b.y);
    *(__half2*)(d + 4) = __floats2half2_rn(a.z, b.z);
    *(__half2*)(d + 6) = __floats2half2_rn(a.w, b.w);
}

// ---------------- HMMA fp16 GEMM, 128x128 tile, GBK=64, ring-3, 2 CTAs/SM ----------------
// B operand in native [K][N] layout, consumed via ldmatrix.trans (attention-V pattern).
// MODE 0: fp32 out (+R residual);  MODE 2: half out + RoPE for n<2*DIMV;
// MODE 3: swiglu (B col-interleaved w1/w3), half out at col n/2
#define GBM 128
#define GBN 128
#define GBK 64
#define APAD 72                    // A row stride (halves): 144B, conflict-free
#define BPAD 136                   // B row stride (halves): 272B, conflict-free (== KVS)
#define A_TILE_H (128*APAD)        // 9216 halves
#define B_TILE_H (64*BPAD)         // 8704 halves
#define STAGE_H (A_TILE_H + B_TILE_H)

template <int MODE>
__global__ __launch_bounds__(256, 2) void gemm_hmma(
    const __half* __restrict__ A, const __half* __restrict__ B,
    const float* __restrict__ R, float* __restrict__ Cf, __half* __restrict__ Ch,
    const float* __restrict__ cs, const float* __restrict__ sn,
    int Mn, int Nn, int Kn)
{
    extern __shared__ __half hs[];
    const int tid = threadIdx.x;
    const int lane = tid & 31, wid = tid >> 5;
    const int wm = wid >> 2, wn = wid & 3;
    const int bm = blockIdx.y * GBM, bn = blockIdx.x * GBN;

    float acc[4][4][4];
    #pragma unroll
    for (int i = 0; i < 4; i++)
        #pragma unroll
        for (int j = 0; j < 4; j++)
            #pragma unroll
            for (int q = 0; q < 4; q++) acc[i][j][q] = 0.f;

    const __half* Ag = A + (size_t)bm * Kn;
    const __half* Bg = B + bn;
    const int r0a = tid >> 3, c0a = (tid & 7) * 8;    // A: 32 rows/pass
    const int r0b = tid >> 4, c0b = (tid & 15) * 8;   // B: 16 rows/pass
    const uint32_t s0a = smem_u32(hs);
    const int NC = Kn / GBK;

#define ISSUE(stage, c)                                                              \
    {                                                                                \
        int kb = (c) * GBK;                                                          \
        uint32_t sA = s0a + (stage) * STAGE_H * 2;                                   \
        uint32_t sB = sA + A_TILE_H * 2;                                             \
        _Pragma("unroll")                                                            \
        for (int ii = 0; ii < 4; ii++) {                                             \
            int arow = r0a + ii * 32;                                                \
            asm volatile("cp.async.cg.shared.global [%0], [%1], 16;"                 \
                :: "r"(sA + (arow * APAD + c0a) * 2), "l"(Ag + (size_t)arow * Kn + kb + c0a)); \
            int brow = r0b + ii * 16;                                                \
            asm volatile("cp.async.cg.shared.global [%0], [%1], 16;"                 \
                :: "r"(sB + (brow * BPAD + c0b) * 2), "l"(Bg + (size_t)(kb + brow) * Nn + c0b)); \
        }                                                                            \
        asm volatile("cp.async.commit_group;" ::: "memory");                         \
    }

    ISSUE(0, 0);
    ISSUE(1, 1);

    for (int c = 0; c < NC; c++) {
        const int s = c - (c / 3) * 3;   // c % 3
        if (c + 1 < NC) asm volatile("cp.async.wait_group 1;" ::: "memory");
        else            asm volatile("cp.async.wait_group 0;" ::: "memory");
        __syncthreads();
        if (c + 2 < NC) {
            int s2 = (c + 2) - ((c + 2) / 3) * 3;
            ISSUE(s2, c + 2);
        }
        const uint32_t aBase = s0a + s * STAGE_H * 2;
        const uint32_t bBase = aBase + A_TILE_H * 2;
        #pragma unroll
        for (int kk = 0; kk < 4; kk++) {
            uint32_t afr[4][4], bfr[4][2];
            #pragma unroll
            for (int mi = 0; mi < 4; mi++) {
                int row = wm * 64 + mi * 16 + (lane & 15);
                int col = kk * 16 + (lane >> 4) * 8;
                ldsm_x4(afr[mi], aBase + (row * APAD + col) * 2);
            }
            #pragma unroll
            for (int jp = 0; jp < 2; jp++) {
                uint32_t t4[4];
                uint32_t addr = bBase + (uint32_t)((kk * 16 + (lane & 15)) * BPAD
                                + wn * 32 + (jp * 2 + (lane >> 4)) * 8) * 2;
                ldsm_x4_t(t4, addr);
                bfr[jp*2][0] = t4[0]; bfr[jp*2][1] = t4[1];
                bfr[jp*2+1][0] = t4[2]; bfr[jp*2+1][1] = t4[3];
            }
            #pragma unroll
            for (int mi = 0; mi < 4; mi++)
                #pragma unroll
                for (int ni = 0; ni < 4; ni++)
                    mma16816(acc[mi][ni], afr[mi], bfr[ni]);
        }
    }
#undef ISSUE

    #pragma unroll
    for (int mi = 0; mi < 4; mi++) {
        int mrow0 = bm + wm * 64 + mi * 16 + (lane >> 2);
        #pragma unroll
        for (int hh = 0; hh < 2; hh++) {
            int m = mrow0 + hh * 8;
            int nb = bn + wn * 32 + 2 * (lane & 3);
            #pragma unroll
            for (int ni = 0; ni < 4; ni++) {
                int n = nb + ni * 8;
                float va = acc[mi][ni][hh * 2 + 0], vb = acc[mi][ni][hh * 2 + 1];
                if (MODE == 0) {
                    size_t off = (size_t)m * Nn + n;
                    if (R) {
                        float2 rv = *(const float2*)(R + off);
                        va += rv.x; vb += rv.y;
                    }
                    *(float2*)(Cf + off) = make_float2(va, vb);
                } else if (MODE == 2) {
                    size_t off = (size_t)m * Nn + n;
                    if (n < 2 * DIMV) {
                        int i2 = (n & (HD - 1)) >> 1;
                        int sidx = m & (SEQ - 1);
                        float cc = cs[sidx * (HD / 2) + i2];
                        float si = sn[sidx * (HD / 2) + i2];
                        float ra = va * cc - vb * si;
                        float rb = va * si + vb * cc;
                        *(__half2*)(Ch + off) = __floats2half2_rn(ra, rb);
                    } else {
                        *(__half2*)(Ch + off) = __floats2half2_rn(va, vb);
                    }
                } else {  // swiglu
                    float g = va / (1.f + __expf(-va)) * vb;
                    Ch[(size_t)m * (Nn >> 1) + (n >> 1)] = __float2half(g);
                }
            }
        }
    }
}

// ---------------- Flash attention, fp16 mma, causal, ring-3, exp2 softmax ----------------
#define BQ  128
#define BKV 64
#define KVS 136

__global__ __launch_bounds__(256) void attn_mma(
    const __half* __restrict__ QKV, __half* __restrict__ O)
{
    extern __shared__ __half kvsm[];
    __half* Ks = kvsm;
    __half* Vs = kvsm + 3 * BKV * KVS;
    const int tid = threadIdx.x, lane = tid & 31, w = tid >> 5;
    const int qt = gridDim.x - 1 - blockIdx.x;
    const int bh = blockIdx.y;
    const int b = bh >> 4, h = bh & 15;
    const int q0 = qt * BQ;
    const int r = lane >> 2, cq = (lane & 3) * 2;
    const float scale2 = 0.08838834764831845f * 1.4426950408889634f;

    uint32_t qf[8][4];
    {
        const __half* Qg  = QKV + (size_t)(b * SEQ + q0 + w * 16 + r) * QKVS + h * HD;
        const __half* Qg8 = Qg + 8 * (size_t)QKVS;
        #pragma unroll
        for (int kk = 0; kk < 8; kk++) {
            qf[kk][0] = *(const uint32_t*)(Qg  + kk * 16 + cq);
            qf[kk][1] = *(const uint32_t*)(Qg8 + kk * 16 + cq);
            qf[kk][2] = *(const uint32_t*)(Qg  + kk * 16 + 8 + cq);
            qf[kk][3] = *(const uint32_t*)(Qg8 + kk * 16 + 8 + cq);
        }
    }

    float oacc[16][4];
    #pragma unroll
    for (int j = 0; j < 16; j++)
        #pragma unroll
        for (int q = 0; q < 4; q++) oacc[j][q] = 0.f;
    float m0 = -1e30f, m1 = -1e30f, l0 = 0.f, l1 = 0.f;

    const uint32_t sKs = smem_u32(Ks), sVs = smem_u32(Vs);
    const __half* Kg = QKV + (size_t)(b * SEQ) * QKVS + DIMV + h * HD;
    const __half* Vg = QKV + (size_t)(b * SEQ) * QKVS + 2 * DIMV + h * HD;
    const int nkt = qt * 2 + 2;

#define KV_ISSUE(stage, kt)                                                        \
    {                                                                              \
        _Pragma("unroll")                                                          \
        for (int ii = 0; ii < 4; ii++) {                                           \
            int idx = tid + ii * 256;                                              \
            int rr = idx >> 4, cc = (idx & 15) * 8;                                \
            uint32_t doff = (uint32_t)(((stage) * BKV + rr) * KVS + cc) * 2;       \
            asm volatile("cp.async.cg.shared.global [%0], [%1], 16;"               \
                :: "r"(sKs + doff), "l"(Kg + (size_t)((kt) * BKV + rr) * QKVS + cc)); \
            asm volatile("cp.async.cg.shared.global [%0], [%1], 16;"               \
                :: "r"(sVs + doff), "l"(Vg + (size_t)((kt) * BKV + rr) * QKVS + cc)); \
        }                                                                          \
        asm volatile("cp.async.commit_group;" ::: "memory");                       \
    }

    KV_ISSUE(0, 0);
    if (nkt > 1) KV_ISSUE(1, 1);

    for (int kt = 0; kt < nkt; kt++) {
        const int s = kt - (kt / 3) * 3;
        if (kt + 1 < nkt) asm volatile("cp.async.wait_group 1;" ::: "memory");
        else              asm volatile("cp.async.wait_group 0;" ::: "memory");
        __syncthreads();
        if (kt + 2 < nkt) {
            int s2 = (kt + 2) - ((kt + 2) / 3) * 3;
            KV_ISSUE(s2, kt + 2);
        }
        const uint32_t kb = sKs + (uint32_t)(s * BKV * KVS) * 2;
        const uint32_t vb = sVs + (uint32_t)(s * BKV * KVS) * 2;

        float sa[8][4];
        #pragma unroll
        for (int j = 0; j < 8; j++)
            #pragma unroll
            for (int q = 0; q < 4; q++) sa[j][q] = 0.f;
        #pragma unroll
        for (int kk = 0; kk < 8; kk++) {
            uint32_t kf[8][2];
            #pragma unroll
            for (int jp = 0; jp < 4; jp++) {
                uint32_t t4[4];
                int nt = jp * 2 + (lane >> 4);
                uint32_t addr = kb + (uint32_t)((nt * 8 + (lane & 7)) * KVS
                                + kk * 16 + ((lane >> 3) & 1) * 8) * 2;
                ldsm_x4(t4, addr);
                kf[jp*2][0] = t4[0]; kf[jp*2][1] = t4[1];
                kf[jp*2+1][0] = t4[2]; kf[jp*2+1][1] = t4[3];
            }
            #pragma unroll
            for (int j = 0; j < 8; j++)
                mma16816(sa[j], qf[kk], kf[j]);
        }

        const int row0 = q0 + w * 16 + r, row1 = row0 + 8;
        const bool need_mask = (kt * BKV + BKV - 1) > row0 || (kt * BKV + BKV - 1) > row1;
        float mx0 = -1e30f, mx1 = -1e30f;
        #pragma unroll
        for (int j = 0; j < 8; j++) {
            int col = kt * BKV + j * 8 + cq;
            sa[j][0] *= scale2; sa[j][1] *= scale2;
            sa[j][2] *= scale2; sa[j][3] *= scale2;
            if (need_mask) {
                if (col     > row0) sa[j][0] = -1e30f;
                if (col + 1 > row0) sa[j][1] = -1e30f;
                if (col     > row1) sa[j][2] = -1e30f;
                if (col + 1 > row1) sa[j][3] = -1e30f;
            }
            mx0 = fmaxf(mx0, fmaxf(sa[j][0], sa[j][1]));
            mx1 = fmaxf(mx1, fmaxf(sa[j][2], sa[j][3]));
        }
        mx0 = fmaxf(mx0, __shfl_xor_sync(0xffffffffu, mx0, 1));
        mx0 = fmaxf(mx0, __shfl_xor_sync(0xffffffffu, mx0, 2));
        mx1 = fmaxf(mx1, __shfl_xor_sync(0xffffffffu, mx1, 1));
        mx1 = fmaxf(mx1, __shfl_xor_sync(0xffffffffu, mx1, 2));
        float mn0 = fmaxf(m0, mx0), mn1 = fmaxf(m1, mx1);
        float a0 = exp2f(m0 - mn0), a1 = exp2f(m1 - mn1);
        float s0 = 0.f, s1 = 0.f;
        uint32_t ph[8][2];
        #pragma unroll
        for (int j = 0; j < 8; j++) {
            float p00 = exp2f(sa[j][0] - mn0);
            float p01 = exp2f(sa[j][1] - mn0);
            float p10 = exp2f(sa[j][2] - mn1);
            float p11 = exp2f(sa[j][3] - mn1);
            s0 += p00 + p01; s1 += p10 + p11;
            ph[j][0] = h2_to_u32(__floats2half2_rn(p00, p01));
            ph[j][1] = h2_to_u32(__floats2half2_rn(p10, p11));
        }
        s0 += __shfl_xor_sync(0xffffffffu, s0, 1);
        s0 += __shfl_xor_sync(0xffffffffu, s0, 2);
        s1 += __shfl_xor_sync(0xffffffffu, s1, 1);
        s1 += __shfl_xor_sync(0xffffffffu, s1, 2);
        l0 = l0 * a0 + s0; l1 = l1 * a1 + s1;
        m0 = mn0; m1 = mn1;
        #pragma unroll
        for (int j = 0; j < 16; j++) {
            oacc[j][0] *= a0; oacc[j][1] *= a0;
            oacc[j][2] *= a1; oacc[j][3] *= a1;
        }

        #pragma unroll
        for (int kk2 = 0; kk2 < 4; kk2++) {
            uint32_t pa[4] = { ph[kk2*2][0], ph[kk2*2][1], ph[kk2*2+1][0], ph[kk2*2+1][1] };
            #pragma unroll
            for (int jp = 0; jp < 8; jp++) {
                uint32_t vt[4];
                uint32_t addr = vb + (uint32_t)((kk2 * 16 + (lane & 15)) * KVS
                                + (jp * 2 + (lane >> 4)) * 8) * 2;
                ldsm_x4_t(vt, addr);
                mma16816(oacc[jp*2],     pa, &vt[0]);
                mma16816(oacc[jp*2 + 1], pa, &vt[2]);
            }
        }
    }
#undef KV_ISSUE

    float i0 = 1.f / l0, i1 = 1.f / l1;
    __half* Og  = O + (size_t)(b * SEQ + q0 + w * 16 + r) * DIMV + h * HD + cq;
    __half* Og8 = Og + 8 * (size_t)DIMV;
    #pragma unroll
    for (int j = 0; j < 16; j++) {
        *(__half2*)(Og  + j * 8) = __floats2half2_rn(oacc[j][0] * i0, oacc[j][1] * i0);
        *(__half2*)(Og8 + j * 8) = __floats2half2_rn(oacc[j][2] * i1, oacc[j][3] * i1);
    }
}

// ---------------- launch ----------------
extern "C" void kernel_launch(void* const* d_in, const int* in_sizes, int n_in,
                              void* d_out, int out_size)
{
    const float* x    = (const float*)d_in[0];
    const float* fcos = (const float*)d_in[1];
    const float* fsin = (const float*)d_in[2];
    const float* wq   = (const float*)d_in[4];
    const float* wk   = (const float*)d_in[5];
    const float* wv   = (const float*)d_in[6];
    const float* wo   = (const float*)d_in[7];
    const float* w1   = (const float*)d_in[8];
    const float* w2   = (const float*)d_in[9];
    const float* w3   = (const float*)d_in[10];
    const float* anw  = (const float*)d_in[11];
    const float* fnw  = (const float*)d_in[12];
    float* out = (float*)d_out;

    __half *xnh, *qkv, *ath, *g1h;
    float *h;
    __half *wqkvKN, *woKN, *w13i, *w2KN;
    cudaGetSymbolAddress((void**)&xnh,    g_xnh);
    cudaGetSymbolAddress((void**)&qkv,    g_qkv);
    cudaGetSymbolAddress((void**)&ath,    g_ath);
    cudaGetSymbolAddress((void**)&h,      g_h);
    cudaGetSymbolAddress((void**)&g1h,    g_g1h);
    cudaGetSymbolAddress((void**)&wqkvKN, g_wqkvKN);
    cudaGetSymbolAddress((void**)&woKN,   g_woKN);
    cudaGetSymbolAddress((void**)&w13i,   g_w13i);
    cudaGetSymbolAddress((void**)&w2KN,   g_w2KN);

    const int gemm_smem = 3 * STAGE_H * (int)sizeof(__half);   // 107520
    cudaFuncSetAttribute(gemm_hmma<0>, cudaFuncAttributeMaxDynamicSharedMemorySize, gemm_smem);
    cudaFuncSetAttribute(gemm_hmma<2>, cudaFuncAttributeMaxDynamicSharedMemorySize, gemm_smem);
    cudaFuncSetAttribute(gemm_hmma<3>, cudaFuncAttributeMaxDynamicSharedMemorySize, gemm_smem);
    const int attn_smem = 6 * BKV * KVS * (int)sizeof(__half);  // 104448
    cudaFuncSetAttribute(attn_mma, cudaFuncAttributeMaxDynamicSharedMemorySize, attn_smem);

    // launches 0-3: fp32->half converts for qkv concat + wo (coalesced streaming)
    {
        int blocks = (DIMV * DIMV) / 2048;   // 8 elems/thread, 256 threads
        convf2h_kernel<<<blocks, 256>>>(wq, wqkvKN, DIMV, QKVS, 0);
        convf2h_kernel<<<blocks, 256>>>(wk, wqkvKN, DIMV, QKVS, DIMV);
        convf2h_kernel<<<blocks, 256>>>(wv, wqkvKN, DIMV, QKVS, 2 * DIMV);
        convf2h_kernel<<<blocks, 256>>>(wo, woKN, DIMV, DIMV, 0);
    }

    // launch 4: rmsnorm
    rmsnorm_kernel<<<MTOT, 256>>>(x, anw, xnh);

    // launch 5: qkv GEMM (profiled by ncu -s 5 -c 1)
    gemm_hmma<2><<<dim3(QKVS / GBN, MTOT / GBM), 256, gemm_smem>>>(
        xnh, wqkvKN, nullptr, nullptr, qkv, fcos, fsin, MTOT, QKVS, DIMV);

    // launch 6: attention
    attn_mma<<<dim3(SEQ / BQ, BATCH * NHEADS), 256, attn_smem>>>(qkv, ath);

    // launches 7-8: FFN weight preps
    conv_interleave_kernel<<<(DIMV * HIDDEN) / 1024, 256>>>(w1, w3, w13i, HIDDEN);
    convf2h_kernel<<<(HIDDEN * DIMV) / 2048, 256>>>(w2, w2KN, DIMV, DIMV, 0);

    // h = x + at @ wo
    gemm_hmma<0><<<dim3(DIMV / GBN, MTOT / GBM), 256, gemm_smem>>>(
        ath, woKN, x, h, nullptr, nullptr, nullptr, MTOT, DIMV, DIMV);

    // hn = rmsnorm(h)
    rmsnorm_kernel<<<MTOT, 256>>>(h, fnw, xnh);

    // g1 = silu(hn@w1) * (hn@w3)
    gemm_hmma<3><<<dim3(2 * HIDDEN / GBN, MTOT / GBM), 256, gemm_smem>>>(
        xnh, w13i, nullptr, nullptr, g1h, nullptr, nullptr, MTOT, 2 * HIDDEN, DIMV);

    // out = h + g1 @ w2
    gemm_hmma<0><<<dim3(DIMV / GBN, MTOT / GBM), 256, gemm_smem>>>(
        g1h, w2KN, h, out, nullptr, nullptr, nullptr, MTOT, DIMV, HIDDEN);
}

// round 17
// speedup vs baseline: 1.0286x; 1.0134x over previous
#include <cuda_runtime.h>
#include <cuda_fp16.h>
#include <math.h>
#include <stdint.h>

#define DIMV    2048
#define NHEADS  16
#define HD      128
#define HIDDEN  8192
#define BATCH   2
#define SEQ     2048
#define MTOT    (BATCH*SEQ)
#define QKVS    (3*DIMV)
#define EPSV    1e-6f

// ---------------- scratch ----------------
__device__ __half g_xnh  [MTOT*DIMV];
__device__ __half g_qkv  [MTOT*QKVS];
__device__ __half g_ath  [MTOT*DIMV];
__device__ float  g_h    [MTOT*DIMV];
__device__ __half g_g1h  [MTOT*HIDDEN];
__device__ __half g_wqkvKN[DIMV*QKVS];      // [K=2048][N=6144] concat q|k|v
__device__ __half g_woKN [DIMV*DIMV];       // [K][N]
__device__ __half g_w13i [DIMV*2*HIDDEN];   // [K][16384] interleaved w1/w3 cols
__device__ __half g_w2KN [HIDDEN*DIMV];     // [K=8192][N=2048]

__device__ __forceinline__ uint32_t smem_u32(const void* p) {
    uint32_t a;
    asm("{ .reg .u64 t; cvta.to.shared.u64 t, %1; cvt.u32.u64 %0, t; }" : "=r"(a) : "l"(p));
    return a;
}
__device__ __forceinline__ uint32_t h2_to_u32(__half2 h) {
    union { __half2 h2; uint32_t u; } cvt;
    cvt.h2 = h;
    return cvt.u;
}
__device__ __forceinline__ void mma16816(float* c, const uint32_t* a, const uint32_t* b) {
    asm volatile("mma.sync.aligned.m16n8k16.row.col.f32.f16.f16.f32 "
        "{%0,%1,%2,%3}, {%4,%5,%6,%7}, {%8,%9}, {%0,%1,%2,%3};"
        : "+f"(c[0]), "+f"(c[1]), "+f"(c[2]), "+f"(c[3])
        : "r"(a[0]), "r"(a[1]), "r"(a[2]), "r"(a[3]), "r"(b[0]), "r"(b[1]));
}
__device__ __forceinline__ void ldsm_x4(uint32_t* r, uint32_t addr) {
    asm volatile("ldmatrix.sync.aligned.m8n8.x4.shared.b16 {%0,%1,%2,%3}, [%4];"
        : "=r"(r[0]), "=r"(r[1]), "=r"(r[2]), "=r"(r[3]) : "r"(addr));
}
__device__ __forceinline__ void ldsm_x4_t(uint32_t* r, uint32_t addr) {
    asm volatile("ldmatrix.sync.aligned.m8n8.x4.trans.shared.b16 {%0,%1,%2,%3}, [%4];"
        : "=r"(r[0]), "=r"(r[1]), "=r"(r[2]), "=r"(r[3]) : "r"(addr));
}

// ---------------- RMSNorm (fp32 in, half out) ----------------
__global__ __launch_bounds__(256) void rmsnorm_kernel(
    const float* __restrict__ x, const float* __restrict__ w, __half* __restrict__ y)
{
    int row = blockIdx.x;
    const float* xr = x + (size_t)row * DIMV;
    float ss = 0.f;
    for (int i = threadIdx.x * 4; i < DIMV; i += blockDim.x * 4) {
        float4 v = *(const float4*)(xr + i);
        ss += v.x*v.x + v.y*v.y + v.z*v.z + v.w*v.w;
    }
    __shared__ float red[8];
    for (int o = 16; o > 0; o >>= 1) ss += __shfl_down_sync(0xffffffffu, ss, o);
    int warp = threadIdx.x >> 5, lane = threadIdx.x & 31;
    if (lane == 0) red[warp] = ss;
    __syncthreads();
    if (warp == 0) {
        float t = (lane < 8) ? red[lane] : 0.f;
        for (int o = 4; o > 0; o >>= 1) t += __shfl_down_sync(0xffffffffu, t, o);
        if (lane == 0) red[0] = t;
    }
    __syncthreads();
    float r = rsqrtf(red[0] / (float)DIMV + EPSV);
    __half* yr = y + (size_t)row * DIMV;
    for (int i = threadIdx.x * 4; i < DIMV; i += blockDim.x * 4) {
        float4 v = *(const float4*)(xr + i);
        float4 ww = *(const float4*)(w + i);
        *(__half2*)(yr + i)     = __floats2half2_rn(v.x * r * ww.x, v.y * r * ww.y);
        *(__half2*)(yr + i + 2) = __floats2half2_rn(v.z * r * ww.z, v.w * r * ww.w);
    }
}

// ---------------- fp32 -> half streaming convert (keeps [K][N] layout; row restride) ----------------
__global__ __launch_bounds__(256) void convf2h_kernel(
    const float* __restrict__ src, __half* __restrict__ dst,
    int N, int dstStride, int dstOff)
{
    size_t i = ((size_t)blockIdx.x * 256 + threadIdx.x) * 8;
    int k = (int)(i / N);
    int n = (int)(i - (size_t)k * N);
    float4 a = *(const float4*)(src + i);
    float4 b = *(const float4*)(src + i + 4);
    __half* d = dst + (size_t)k * dstStride + dstOff + n;
    *(__half2*)(d)     = __floats2half2_rn(a.x, a.y);
    *(__half2*)(d + 2) = __floats2half2_rn(a.z, a.w);
    *(__half2*)(d + 4) = __floats2half2_rn(b.x, b.y);
    *(__half2*)(d + 6) = __floats2half2_rn(b.z, b.w);
}

// interleave w1/w3 columns: dst[k][2j]=w1[k][j], dst[k][2j+1]=w3[k][j]
__global__ __launch_bounds__(256) void conv_interleave_kernel(
    const float* __restrict__ w1, const float* __restrict__ w3,
    __half* __restrict__ dst, int N)
{
    size_t i = ((size_t)blockIdx.x * 256 + threadIdx.x) * 4;
    float4 a = *(const float4*)(w1 + i);
    float4 b = *(const float4*)(w3 + i);
    __half* d = dst + i * 2;
    *(__half2*)(d)     = __floats2half2_rn(a.x, b.x);
    *(__half2*)(d + 2) = __floats2half2_rn(a.y, b.y);
    *(__half2*)(d + 4) = __floats2half2_rn(a.z, b.z);
    *(__half2*)(d + 6) = __floats2half2_rn(a.w, b.w);
}

// ---------------- HMMA fp16 GEMM, 128x128 tile, GBK=64, ring-3, 2 CTAs/SM ----------------
// B operand in native [K][N] layout, consumed via ldmatrix.trans (attention-V pattern).
#define GBM 128
#define GBN 128
#define GBK 64
#define APAD 72
#define BPAD 136
#define A_TILE_H (128*APAD)
#define B_TILE_H (64*BPAD)
#define STAGE_H (A_TILE_H + B_TILE_H)

template <int MODE>
__global__ __launch_bounds__(256, 2) void gemm_hmma(
    const __half* __restrict__ A, const __half* __restrict__ B,
    const float* __restrict__ R, float* __restrict__ Cf, __half* __restrict__ Ch,
    const float* __restrict__ cs, const float* __restrict__ sn,
    int Mn, int Nn, int Kn)
{
    extern __shared__ __half hs[];
    const int tid = threadIdx.x;
    const int lane = tid & 31, wid = tid >> 5;
    const int wm = wid >> 2, wn = wid & 3;
    const int bm = blockIdx.y * GBM, bn = blockIdx.x * GBN;

    float acc[4][4][4];
    #pragma unroll
    for (int i = 0; i < 4; i++)
        #pragma unroll
        for (int j = 0; j < 4; j++)
            #pragma unroll
            for (int q = 0; q < 4; q++) acc[i][j][q] = 0.f;

    const __half* Ag = A + (size_t)bm * Kn;
    const __half* Bg = B + bn;
    const int r0a = tid >> 3, c0a = (tid & 7) * 8;
    const int r0b = tid >> 4, c0b = (tid & 15) * 8;
    const uint32_t s0a = smem_u32(hs);
    const int NC = Kn / GBK;

#define ISSUE(stage, c)                                                              \
    {                                                                                \
        int kb = (c) * GBK;                                                          \
        uint32_t sA = s0a + (stage) * STAGE_H * 2;                                   \
        uint32_t sB = sA + A_TILE_H * 2;                                             \
        _Pragma("unroll")                                                            \
        for (int ii = 0; ii < 4; ii++) {                                             \
            int arow = r0a + ii * 32;                                                \
            asm volatile("cp.async.cg.shared.global [%0], [%1], 16;"                 \
                :: "r"(sA + (arow * APAD + c0a) * 2), "l"(Ag + (size_t)arow * Kn + kb + c0a)); \
            int brow = r0b + ii * 16;                                                \
            asm volatile("cp.async.cg.shared.global [%0], [%1], 16;"                 \
                :: "r"(sB + (brow * BPAD + c0b) * 2), "l"(Bg + (size_t)(kb + brow) * Nn + c0b)); \
        }                                                                            \
        asm volatile("cp.async.commit_group;" ::: "memory");                         \
    }

    ISSUE(0, 0);
    ISSUE(1, 1);

    for (int c = 0; c < NC; c++) {
        const int s = c - (c / 3) * 3;
        if (c + 1 < NC) asm volatile("cp.async.wait_group 1;" ::: "memory");
        else            asm volatile("cp.async.wait_group 0;" ::: "memory");
        __syncthreads();
        if (c + 2 < NC) {
            int s2 = (c + 2) - ((c + 2) / 3) * 3;
            ISSUE(s2, c + 2);
        }
        const uint32_t aBase = s0a + s * STAGE_H * 2;
        const uint32_t bBase = aBase + A_TILE_H * 2;
        #pragma unroll
        for (int kk = 0; kk < 4; kk++) {
            uint32_t afr[4][4], bfr[4][2];
            #pragma unroll
            for (int mi = 0; mi < 4; mi++) {
                int row = wm * 64 + mi * 16 + (lane & 15);
                int col = kk * 16 + (lane >> 4) * 8;
                ldsm_x4(afr[mi], aBase + (row * APAD + col) * 2);
            }
            #pragma unroll
            for (int jp = 0; jp < 2; jp++) {
                uint32_t t4[4];
                uint32_t addr = bBase + (uint32_t)((kk * 16 + (lane & 15)) * BPAD
                                + wn * 32 + (jp * 2 + (lane >> 4)) * 8) * 2;
                ldsm_x4_t(t4, addr);
                bfr[jp*2][0] = t4[0]; bfr[jp*2][1] = t4[1];
                bfr[jp*2+1][0] = t4[2]; bfr[jp*2+1][1] = t4[3];
            }
            #pragma unroll
            for (int mi = 0; mi < 4; mi++)
                #pragma unroll
                for (int ni = 0; ni < 4; ni++)
                    mma16816(acc[mi][ni], afr[mi], bfr[ni]);
        }
    }
#undef ISSUE

    #pragma unroll
    for (int mi = 0; mi < 4; mi++) {
        int mrow0 = bm + wm * 64 + mi * 16 + (lane >> 2);
        #pragma unroll
        for (int hh = 0; hh < 2; hh++) {
            int m = mrow0 + hh * 8;
            int nb = bn + wn * 32 + 2 * (lane & 3);
            #pragma unroll
            for (int ni = 0; ni < 4; ni++) {
                int n = nb + ni * 8;
                float va = acc[mi][ni][hh * 2 + 0], vb = acc[mi][ni][hh * 2 + 1];
                if (MODE == 0) {
                    size_t off = (size_t)m * Nn + n;
                    if (R) {
                        float2 rv = *(const float2*)(R + off);
                        va += rv.x; vb += rv.y;
                    }
                    *(float2*)(Cf + off) = make_float2(va, vb);
                } else if (MODE == 2) {
                    size_t off = (size_t)m * Nn + n;
                    if (n < 2 * DIMV) {
                        int i2 = (n & (HD - 1)) >> 1;
                        int sidx = m & (SEQ - 1);
                        float cc = cs[sidx * (HD / 2) + i2];
                        float si = sn[sidx * (HD / 2) + i2];
                        float ra = va * cc - vb * si;
                        float rb = va * si + vb * cc;
                        *(__half2*)(Ch + off) = __floats2half2_rn(ra, rb);
                    } else {
                        *(__half2*)(Ch + off) = __floats2half2_rn(va, vb);
                    }
                } else {  // swiglu
                    float g = va / (1.f + __expf(-va)) * vb;
                    Ch[(size_t)m * (Nn >> 1) + (n >> 1)] = __float2half(g);
                }
            }
        }
    }
}

// ---------------- Flash attention, fp16 mma, causal, ring-3, exp2 softmax ----------------
#define BQ  128
#define BKV 64
#define KVS 136

__global__ __launch_bounds__(256) void attn_mma(
    const __half* __restrict__ QKV, __half* __restrict__ O)
{
    extern __shared__ __half kvsm[];
    __half* Ks = kvsm;
    __half* Vs = kvsm + 3 * BKV * KVS;
    const int tid = threadIdx.x, lane = tid & 31, w = tid >> 5;
    const int qt = gridDim.x - 1 - blockIdx.x;
    const int bh = blockIdx.y;
    const int b = bh >> 4, h = bh & 15;
    const int q0 = qt * BQ;
    const int r = lane >> 2, cq = (lane & 3) * 2;
    const float scale2 = 0.08838834764831845f * 1.4426950408889634f;

    uint32_t qf[8][4];
    {
        const __half* Qg  = QKV + (size_t)(b * SEQ + q0 + w * 16 + r) * QKVS + h * HD;
        const __half* Qg8 = Qg + 8 * (size_t)QKVS;
        #pragma unroll
        for (int kk = 0; kk < 8; kk++) {
            qf[kk][0] = *(const uint32_t*)(Qg  + kk * 16 + cq);
            qf[kk][1] = *(const uint32_t*)(Qg8 + kk * 16 + cq);
            qf[kk][2] = *(const uint32_t*)(Qg  + kk * 16 + 8 + cq);
            qf[kk][3] = *(const uint32_t*)(Qg8 + kk * 16 + 8 + cq);
        }
    }

    float oacc[16][4];
    #pragma unroll
    for (int j = 0; j < 16; j++)
        #pragma unroll
        for (int q = 0; q < 4; q++) oacc[j][q] = 0.f;
    float m0 = -1e30f, m1 = -1e30f, l0 = 0.f, l1 = 0.f;

    const uint32_t sKs = smem_u32(Ks), sVs = smem_u32(Vs);
    const __half* Kg = QKV + (size_t)(b * SEQ) * QKVS + DIMV + h * HD;
    const __half* Vg = QKV + (size_t)(b * SEQ) * QKVS + 2 * DIMV + h * HD;
    const int nkt = qt * 2 + 2;

#define KV_ISSUE(stage, kt)                                                        \
    {                                                                              \
        _Pragma("unroll")                                                          \
        for (int ii = 0; ii < 4; ii++) {                                           \
            int idx = tid + ii * 256;                                              \
            int rr = idx >> 4, cc = (idx & 15) * 8;                                \
            uint32_t doff = (uint32_t)(((stage) * BKV + rr) * KVS + cc) * 2;       \
            asm volatile("cp.async.cg.shared.global [%0], [%1], 16;"               \
                :: "r"(sKs + doff), "l"(Kg + (size_t)((kt) * BKV + rr) * QKVS + cc)); \
            asm volatile("cp.async.cg.shared.global [%0], [%1], 16;"               \
                :: "r"(sVs + doff), "l"(Vg + (size_t)((kt) * BKV + rr) * QKVS + cc)); \
        }                                                                          \
        asm volatile("cp.async.commit_group;" ::: "memory");                       \
    }

    KV_ISSUE(0, 0);
    if (nkt > 1) KV_ISSUE(1, 1);

    for (int kt = 0; kt < nkt; kt++) {
        const int s = kt - (kt / 3) * 3;
        if (kt + 1 < nkt) asm volatile("cp.async.wait_group 1;" ::: "memory");
        else              asm volatile("cp.async.wait_group 0;" ::: "memory");
        __syncthreads();
        if (kt + 2 < nkt) {
            int s2 = (kt + 2) - ((kt + 2) / 3) * 3;
            KV_ISSUE(s2, kt + 2);
        }
        const uint32_t kb = sKs + (uint32_t)(s * BKV * KVS) * 2;
        const uint32_t vb = sVs + (uint32_t)(s * BKV * KVS) * 2;

        float sa[8][4];
        #pragma unroll
        for (int j = 0; j < 8; j++)
            #pragma unroll
            for (int q = 0; q < 4; q++) sa[j][q] = 0.f;
        #pragma unroll
        for (int kk = 0; kk < 8; kk++) {
            uint32_t kf[8][2];
            #pragma unroll
            for (int jp = 0; jp < 4; jp++) {
                uint32_t t4[4];
                int nt = jp * 2 + (lane >> 4);
                uint32_t addr = kb + (uint32_t)((nt * 8 + (lane & 7)) * KVS
                                + kk * 16 + ((lane >> 3) & 1) * 8) * 2;
                ldsm_x4(t4, addr);
                kf[jp*2][0] = t4[0]; kf[jp*2][1] = t4[1];
                kf[jp*2+1][0] = t4[2]; kf[jp*2+1][1] = t4[3];
            }
            #pragma unroll
            for (int j = 0; j < 8; j++)
                mma16816(sa[j], qf[kk], kf[j]);
        }

        const int row0 = q0 + w * 16 + r, row1 = row0 + 8;
        const bool need_mask = (kt * BKV + BKV - 1) > row0 || (kt * BKV + BKV - 1) > row1;
        float mx0 = -1e30f, mx1 = -1e30f;
        #pragma unroll
        for (int j = 0; j < 8; j++) {
            int col = kt * BKV + j * 8 + cq;
            sa[j][0] *= scale2; sa[j][1] *= scale2;
            sa[j][2] *= scale2; sa[j][3] *= scale2;
            if (need_mask) {
                if (col     > row0) sa[j][0] = -1e30f;
                if (col + 1 > row0) sa[j][1] = -1e30f;
                if (col     > row1) sa[j][2] = -1e30f;
                if (col + 1 > row1) sa[j][3] = -1e30f;
            }
            mx0 = fmaxf(mx0, fmaxf(sa[j][0], sa[j][1]));
            mx1 = fmaxf(mx1, fmaxf(sa[j][2], sa[j][3]));
        }
        mx0 = fmaxf(mx0, __shfl_xor_sync(0xffffffffu, mx0, 1));
        mx0 = fmaxf(mx0, __shfl_xor_sync(0xffffffffu, mx0, 2));
        mx1 = fmaxf(mx1, __shfl_xor_sync(0xffffffffu, mx1, 1));
        mx1 = fmaxf(mx1, __shfl_xor_sync(0xffffffffu, mx1, 2));
        float mn0 = fmaxf(m0, mx0), mn1 = fmaxf(m1, mx1);
        float a0 = exp2f(m0 - mn0), a1 = exp2f(m1 - mn1);
        float s0 = 0.f, s1 = 0.f;
        uint32_t ph[8][2];
        #pragma unroll
        for (int j = 0; j < 8; j++) {
            float p00 = exp2f(sa[j][0] - mn0);
            float p01 = exp2f(sa[j][1] - mn0);
            float p10 = exp2f(sa[j][2] - mn1);
            float p11 = exp2f(sa[j][3] - mn1);
            s0 += p00 + p01; s1 += p10 + p11;
            ph[j][0] = h2_to_u32(__floats2half2_rn(p00, p01));
            ph[j][1] = h2_to_u32(__floats2half2_rn(p10, p11));
        }
        s0 += __shfl_xor_sync(0xffffffffu, s0, 1);
        s0 += __shfl_xor_sync(0xffffffffu, s0, 2);
        s1 += __shfl_xor_sync(0xffffffffu, s1, 1);
        s1 += __shfl_xor_sync(0xffffffffu, s1, 2);
        l0 = l0 * a0 + s0; l1 = l1 * a1 + s1;
        m0 = mn0; m1 = mn1;
        #pragma unroll
        for (int j = 0; j < 16; j++) {
            oacc[j][0] *= a0; oacc[j][1] *= a0;
            oacc[j][2] *= a1; oacc[j][3] *= a1;
        }

        #pragma unroll
        for (int kk2 = 0; kk2 < 4; kk2++) {
            uint32_t pa[4] = { ph[kk2*2][0], ph[kk2*2][1], ph[kk2*2+1][0], ph[kk2*2+1][1] };
            #pragma unroll
            for (int jp = 0; jp < 8; jp++) {
                uint32_t vt[4];
                uint32_t addr = vb + (uint32_t)((kk2 * 16 + (lane & 15)) * KVS
                                + (jp * 2 + (lane >> 4)) * 8) * 2;
                ldsm_x4_t(vt, addr);
                mma16816(oacc[jp*2],     pa, &vt[0]);
                mma16816(oacc[jp*2 + 1], pa, &vt[2]);
            }
        }
    }
#undef KV_ISSUE

    float i0 = 1.f / l0, i1 = 1.f / l1;
    __half* Og  = O + (size_t)(b * SEQ + q0 + w * 16 + r) * DIMV + h * HD + cq;
    __half* Og8 = Og + 8 * (size_t)DIMV;
    #pragma unroll
    for (int j = 0; j < 16; j++) {
        *(__half2*)(Og  + j * 8) = __floats2half2_rn(oacc[j][0] * i0, oacc[j][1] * i0);
        *(__half2*)(Og8 + j * 8) = __floats2half2_rn(oacc[j][2] * i1, oacc[j][3] * i1);
    }
}

// ---------------- launch ----------------
extern "C" void kernel_launch(void* const* d_in, const int* in_sizes, int n_in,
                              void* d_out, int out_size)
{
    const float* x    = (const float*)d_in[0];
    const float* fcos = (const float*)d_in[1];
    const float* fsin = (const float*)d_in[2];
    const float* wq   = (const float*)d_in[4];
    const float* wk   = (const float*)d_in[5];
    const float* wv   = (const float*)d_in[6];
    const float* wo   = (const float*)d_in[7];
    const float* w1   = (const float*)d_in[8];
    const float* w2   = (const float*)d_in[9];
    const float* w3   = (const float*)d_in[10];
    const float* anw  = (const float*)d_in[11];
    const float* fnw  = (const float*)d_in[12];
    float* out = (float*)d_out;

    __half *xnh, *qkv, *ath, *g1h;
    float *h;
    __half *wqkvKN, *woKN, *w13i, *w2KN;
    cudaGetSymbolAddress((void**)&xnh,    g_xnh);
    cudaGetSymbolAddress((void**)&qkv,    g_qkv);
    cudaGetSymbolAddress((void**)&ath,    g_ath);
    cudaGetSymbolAddress((void**)&h,      g_h);
    cudaGetSymbolAddress((void**)&g1h,    g_g1h);
    cudaGetSymbolAddress((void**)&wqkvKN, g_wqkvKN);
    cudaGetSymbolAddress((void**)&woKN,   g_woKN);
    cudaGetSymbolAddress((void**)&w13i,   g_w13i);
    cudaGetSymbolAddress((void**)&w2KN,   g_w2KN);

    const int gemm_smem = 3 * STAGE_H * (int)sizeof(__half);   // 107520
    cudaFuncSetAttribute(gemm_hmma<0>, cudaFuncAttributeMaxDynamicSharedMemorySize, gemm_smem);
    cudaFuncSetAttribute(gemm_hmma<2>, cudaFuncAttributeMaxDynamicSharedMemorySize, gemm_smem);
    cudaFuncSetAttribute(gemm_hmma<3>, cudaFuncAttributeMaxDynamicSharedMemorySize, gemm_smem);
    const int attn_smem = 6 * BKV * KVS * (int)sizeof(__half);  // 104448
    cudaFuncSetAttribute(attn_mma, cudaFuncAttributeMaxDynamicSharedMemorySize, attn_smem);

    // side stream + fork/join events (created once; not device-memory allocation)
    static cudaStream_t side = nullptr;
    static cudaEvent_t evFork = nullptr, evJoin = nullptr;
    if (!side) {
        cudaStreamCreateWithFlags(&side, cudaStreamNonBlocking);
        cudaEventCreateWithFlags(&evFork, cudaEventDisableTiming);
        cudaEventCreateWithFlags(&evJoin, cudaEventDisableTiming);
    }

    // main stream: qkv-critical converts
    {
        int blocks = (DIMV * DIMV) / 2048;
        convf2h_kernel<<<blocks, 256>>>(wq, wqkvKN, DIMV, QKVS, 0);
        convf2h_kernel<<<blocks, 256>>>(wk, wqkvKN, DIMV, QKVS, DIMV);
        convf2h_kernel<<<blocks, 256>>>(wv, wqkvKN, DIMV, QKVS, 2 * DIMV);
    }

    // fork: side stream converts wo / w13 / w2 concurrently with qkv GEMM + attention
    cudaEventRecord(evFork, 0);
    cudaStreamWaitEvent(side, evFork, 0);
    convf2h_kernel<<<(DIMV * DIMV) / 2048, 256, 0, side>>>(wo, woKN, DIMV, DIMV, 0);
    conv_interleave_kernel<<<(DIMV * HIDDEN) / 1024, 256, 0, side>>>(w1, w3, w13i, HIDDEN);
    convf2h_kernel<<<(HIDDEN * DIMV) / 2048, 256, 0, side>>>(w2, w2KN, DIMV, DIMV, 0);
    cudaEventRecord(evJoin, side);

    // main: rmsnorm -> qkv GEMM -> attention
    rmsnorm_kernel<<<MTOT, 256>>>(x, anw, xnh);
    gemm_hmma<2><<<dim3(QKVS / GBN, MTOT / GBM), 256, gemm_smem>>>(
        xnh, wqkvKN, nullptr, nullptr, qkv, fcos, fsin, MTOT, QKVS, DIMV);
    attn_mma<<<dim3(SEQ / BQ, BATCH * NHEADS), 256, attn_smem>>>(qkv, ath);

    // join: side stream converts must be complete before wo GEMM
    cudaStreamWaitEvent(0, evJoin, 0);

    // h = x + at @ wo
    gemm_hmma<0><<<dim3(DIMV / GBN, MTOT / GBM), 256, gemm_smem>>>(
        ath, woKN, x, h, nullptr, nullptr, nullptr, MTOT, DIMV, DIMV);

    // hn = rmsnorm(h)
    rmsnorm_kernel<<<MTOT, 256>>>(h, fnw, xnh);

    // g1 = silu(hn@w1) * (hn@w3)
    gemm_hmma<3><<<dim3(2 * HIDDEN / GBN, MTOT / GBM), 256, gemm_smem>>>(
        xnh, w13i, nullptr, nullptr, g1h, nullptr, nullptr, MTOT, 2 * HIDDEN, DIMV);

    // out = h + g1 @ w2
    gemm_hmma<0><<<dim3(DIMV / GBN, MTOT / GBM), 256, gemm_smem>>>(
        g1h, w2KN, h, out, nullptr, nullptr, nullptr, MTOT, DIMV, HIDDEN);
}